// round 15
// baseline (speedup 1.0000x reference)
#include <cuda_runtime.h>
#include <cuda_bf16.h>
#include <cstdint>

#define NB 512
#define DD 128
#define WW 512
#define TT 512
#define NTHR 512

// float-indexed SMEM layout
#define O_W1 0                         // 64x132 f32 (tf32)   8448
#define O_AM (O_W1+64*132)             // 16x132 f32          2112
#define O_Z  (O_AM+16*132)             // 32x132 f32          4224
#define O_B  (O_Z+4224)                // 144 biases
#define O_TS (O_B+144)                 // 512 ts
#define O_KS (O_TS+512)                // 5 x (32x128) bf16 = 10240 f
#define O_W2H (O_KS+10240)             // bf16 64x520 = 16640 f
#define O_W3H (O_W2H+16640)            // bf16 16x520 = 4160 f
#define O_H1O (O_W3H+4160)             // bf16 32x72 = 1152 f (own H1 slice)
#define O_H2O (O_H1O+1152)             // bf16 32x72 = 1152 f (own H2 slice)
#define O_PT  (O_H2O+1152)             // 32x68 f32 partials = 2176 f
#define O_SG  (O_PT+2176)              // 6 x (32x72) bf16 = 6912 f
#define SGF   1152
#define SMF   (O_SG+6912)              // 57872 f = 231488 B (<= 232448)

__device__ __align__(16) __nv_bfloat16 g_h1[NB*WW];
__device__ __align__(16) __nv_bfloat16 g_h2[NB*WW];
__device__ __align__(16) float g_y[NB*DD];

__constant__ float c_AT[6][5] = {
    {0.f,0.f,0.f,0.f,0.f},
    {0.161f,0.f,0.f,0.f,0.f},
    {-0.008480655492356989f,0.335480655492357f,0.f,0.f,0.f},
    {2.8971530571054935f,-6.359448489975075f,4.3622954328695815f,0.f,0.f},
    {5.325864828439257f,-11.748883564062828f,7.4955393428898365f,-0.09249506636175525f,0.f},
    {5.86145544294642f,-12.92096931784711f,8.159367898576159f,-0.071584973281401f,-0.028269050394068383f}};
__constant__ float c_BT[6] = {0.09646076681806523f,0.01f,0.4798896504144996f,
                              1.379008574103742f,-3.290069515436081f,2.324710524099774f};

__device__ __forceinline__ float f2tf32(float x){
    unsigned u; asm("cvt.rna.tf32.f32 %0,%1;":"=r"(u):"f"(x)); return __uint_as_float(u);}
__device__ __forceinline__ float ftanh(float x){
    float e = exp2f(2.885390081777927f * x);
    return 1.0f - __fdividef(2.0f, e + 1.0f);}
__device__ __forceinline__ unsigned pack_bf2(float lo,float hi){
    unsigned r; asm("cvt.rn.bf16x2.f32 %0,%1,%2;":"=r"(r):"f"(hi),"f"(lo)); return r;}
__device__ __forceinline__ void mma8(float* c,const unsigned* a,const unsigned* b){
    asm volatile("mma.sync.aligned.m16n8k8.row.col.f32.tf32.tf32.f32 "
        "{%0,%1,%2,%3},{%4,%5,%6,%7},{%8,%9},{%0,%1,%2,%3};"
        :"+f"(c[0]),"+f"(c[1]),"+f"(c[2]),"+f"(c[3])
        :"r"(a[0]),"r"(a[1]),"r"(a[2]),"r"(a[3]),"r"(b[0]),"r"(b[1]));}
__device__ __forceinline__ void mmab(float* c,const unsigned* a,const unsigned* b){
    asm volatile("mma.sync.aligned.m16n8k16.row.col.f32.bf16.bf16.f32 "
        "{%0,%1,%2,%3},{%4,%5,%6,%7},{%8,%9},{%0,%1,%2,%3};"
        :"+f"(c[0]),"+f"(c[1]),"+f"(c[2]),"+f"(c[3])
        :"r"(a[0]),"r"(a[1]),"r"(a[2]),"r"(a[3]),"r"(b[0]),"r"(b[1]));}
__device__ __forceinline__ unsigned sma(const void* p){
    return (unsigned)__cvta_generic_to_shared(p);}
__device__ __forceinline__ void ldsm4(unsigned r[4], const void* p){
    asm volatile("ldmatrix.sync.aligned.m8n8.x4.shared.b16 {%0,%1,%2,%3},[%4];"
        :"=r"(r[0]),"=r"(r[1]),"=r"(r[2]),"=r"(r[3]):"r"(sma(p)));}
__device__ __forceinline__ void ldsm2(unsigned r[2], const void* p){
    asm volatile("ldmatrix.sync.aligned.m8n8.x2.shared.b16 {%0,%1},[%2];"
        :"=r"(r[0]),"=r"(r[1]):"r"(sma(p)));}
__device__ __forceinline__ void cpa(uint32_t d,const void* s){
    asm volatile("cp.async.cg.shared.global [%0],[%1],16;"::"r"(d),"l"(s):"memory");}
__device__ __forceinline__ void cpc(){asm volatile("cp.async.commit_group;":::"memory");}
__device__ __forceinline__ void carr(){
    asm volatile("barrier.cluster.arrive.aligned;":::"memory");}
__device__ __forceinline__ void cwait(){
    asm volatile("barrier.cluster.wait.aligned;":::"memory");}
__device__ __forceinline__ void stclu(uint32_t laddr,unsigned rr,unsigned v){
    uint32_t ra;
    asm volatile("mapa.shared::cluster.u32 %0,%1,%2;":"=r"(ra):"r"(laddr),"r"(rr));
    asm volatile("st.shared::cluster.u32 [%0],%1;"::"r"(ra),"r"(v):"memory");}
__device__ __forceinline__ void waitg(int i){
    if(i==0)      asm volatile("cp.async.wait_group 5;":::"memory");
    else if(i==1) asm volatile("cp.async.wait_group 4;":::"memory");
    else if(i==2) asm volatile("cp.async.wait_group 4;":::"memory");
    else if(i==3) asm volatile("cp.async.wait_group 3;":::"memory");
    else if(i==4) asm volatile("cp.async.wait_group 2;":::"memory");
    else if(i==5) asm volatile("cp.async.wait_group 1;":::"memory");
    else          asm volatile("cp.async.wait_group 0;":::"memory");}

// tf32 m16n16, 64 K-cols from koff
__device__ __forceinline__ void mmaT16(const float* A,int lda,const float* B,int ldb,
        float acc[2][4],int wm,int wn,int koff,int lane){
    const float* ap = A + (wm+(lane&15))*lda + ((lane>>4)<<2) + koff;
    const float* bp = B + (wn+(lane&7)+((lane>>4)<<3))*ldb + (((lane>>3)&1)<<2) + koff;
#pragma unroll
    for(int kk=0;kk<64;kk+=8){ unsigned a[4],b[4];
        ldsm4(a,ap+kk); ldsm4(b,bp+kk);
        mma8(acc[0],a,b); mma8(acc[1],a,b+2);}}

// tf32 m16n8, 32 K-cols from koff
__device__ __forceinline__ void mmaT8(const float* A,int lda,const float* B,int ldb,
        float acc[4],int wm,int wn8,int koff,int lane){
    const float* ap = A + (wm+(lane&15))*lda + ((lane>>4)<<2) + koff;
    const float* bp = B + (wn8+(lane&7))*ldb + (((lane>>3)&1)<<2) + koff;
#pragma unroll
    for(int kk=0;kk<32;kk+=8){ unsigned a[4],b[2];
        ldsm4(a,ap+kk); ldsm2(b,bp+kk);
        mma8(acc,a,b);}}

// bf16 m16n16, nk k16-steps
__device__ __forceinline__ void mmaB16(const __nv_bfloat16* A,int lda,
        const __nv_bfloat16* B,int ldb,float acc[2][4],int wm,int wn,
        int koffA,int koffB,int lane,int nk){
    const __nv_bfloat16* ap = A + (wm+(lane&15))*lda + ((lane>>4)<<3) + koffA;
    const __nv_bfloat16* bp = B + (wn+(lane&7)+((lane>>4)<<3))*ldb + (((lane>>3)&1)<<3) + koffB;
#pragma unroll
    for(int s=0;s<nk;s++){ unsigned a[4],b[4];
        ldsm4(a,ap+s*16); ldsm4(b,bp+s*16);
        mmab(acc[0],a,b); mmab(acc[1],a,b+2);}}

// bf16 m16n8, nk k16-steps
__device__ __forceinline__ void mmaB8(const __nv_bfloat16* A,int lda,
        const __nv_bfloat16* B,int ldb,float acc[4],int wm,int wn8,
        int koffA,int koffB,int lane,int nk){
    const __nv_bfloat16* ap = A + (wm+(lane&15))*lda + ((lane>>4)<<3) + koffA;
    const __nv_bfloat16* bp = B + (wn8+(lane&7))*ldb + (((lane>>3)&1)<<3) + koffB;
#pragma unroll
    for(int s=0;s<nk;s++){ unsigned a[4],b[2];
        ldsm4(a,ap+s*16); ldsm2(b,bp+s*16);
        mmab(acc,a,b);}}

__global__ void __launch_bounds__(NTHR,1) ode_kernel(
        const float* __restrict__ ts,const float* __restrict__ yi,
        const float* __restrict__ w1,const float* __restrict__ b1,
        const float* __restrict__ w2,const float* __restrict__ b2,
        const float* __restrict__ w3,const float* __restrict__ b3,
        const float* __restrict__ Am,float* __restrict__ out){
    extern __shared__ float sm[];
    __nv_bfloat16* w2h=(__nv_bfloat16*)(sm+O_W2H);
    __nv_bfloat16* w3h=(__nv_bfloat16*)(sm+O_W3H);
    __nv_bfloat16* ksm=(__nv_bfloat16*)(sm+O_KS);
    __nv_bfloat16* h1o=(__nv_bfloat16*)(sm+O_H1O);
    __nv_bfloat16* h2o=(__nv_bfloat16*)(sm+O_H2O);
    __nv_bfloat16* sg =(__nv_bfloat16*)(sm+O_SG);
    float* Zs=sm+O_Z;
    float* pt=sm+O_PT;
    const float* tss=sm+O_TS;

    const int tid=threadIdx.x, wid=tid>>5, lane=tid&31;
    const int gid=lane>>2, tig=lane&3;
    const int wm=(wid&1)*16, wn=((wid>>1)&3)*16, ks2=wid>>3;
    const int wn8=((wid>>1)&1)*8, ks4=wid>>2;
    const int rank=blockIdx.x&7, clus=blockIdx.x>>3;
    const int m0=clus*32, n0h=rank*64, n0k=rank*16;
    const uint32_t ks_sma=sma(ksm);

    // remote group list (7 groups of 64 cols, skipping own)
    int gl[7];
    {   int idx=0;
#pragma unroll
        for(int g=0;g<8;g++) if(g!=rank) gl[idx++]=g; }
    // group staging granule (32 rows x 8 granules of 16B; tid<256 active)
    const int gr=tid>>3, gc=(tid&7)<<3;
    uint32_t sgb[6];
#pragma unroll
    for(int i=0;i<6;i++) sgb[i]=sma(sg+i*SGF*2*0+ i*(32*72)) + (uint32_t)(gr*72+gc)*2u;

    // ---- init ----
    for(int i=tid;i<64*512;i+=NTHR){int n=i>>9,k=i&511;
        w2h[n*520+k]=__float2bfloat16(w2[(size_t)(n0h+n)*WW+k]);}
    for(int i=tid;i<16*512;i+=NTHR){int n=i>>9,k=i&511;
        w3h[n*520+k]=__float2bfloat16(w3[(size_t)(n0k+n)*WW+k]);}
    for(int i=tid;i<64*128;i+=NTHR){int n=i>>7,k=i&127;
        sm[O_W1+n*132+k]=f2tf32(w1[(size_t)(n0h+n)*DD+k]);}
    for(int i=tid;i<16*128;i+=NTHR){int n=i>>7,k=i&127;
        sm[O_AM+n*132+k]=f2tf32(Am[(size_t)(n0k+n)*DD+k]);}
    if(tid<64) sm[O_B+tid]=b1[n0h+tid];
    else if(tid<128) sm[O_B+tid]=b2[n0h+tid-64];
    else if(tid<144) sm[O_B+tid]=b3[n0k+tid-128];
    sm[O_TS+tid]=ts[tid];
    {   int i=rank*NTHR+tid;
        int r=i>>7,c=i&127; float v=yi[(size_t)(m0+r)*DD+c];
        __stcg(g_y+(size_t)(m0+r)*DD+c,v);
        out[(size_t)(m0+r)*TT*DD+c]=v;}
    __syncthreads();
    carr(); cwait();

    const float* b1s=sm+O_B; const float* b2s=sm+O_B+64; const float* b3s=sm+O_B+128;
    const int zr=tid>>4, zc=(tid&15)<<3;
    const int cg=n0k+wn8+2*tig;
    const int r0g=m0+wm+gid;

    float yreg[8];

    for(int t=0;t<TT-1;t++){
        const float h=tss[t+1]-tss[t];
        float yacc[4]={0.f,0.f,0.f,0.f};
        {   const float4* yp=(const float4*)(g_y+(size_t)(m0+zr)*DD+zc);
            float4 a=__ldcg(yp), b=__ldcg(yp+1);
            yreg[0]=a.x;yreg[1]=a.y;yreg[2]=a.z;yreg[3]=a.w;
            yreg[4]=b.x;yreg[5]=b.y;yreg[6]=b.z;yreg[7]=b.w;}
        for(int s=0;s<6;s++){
            float ha[5];
#pragma unroll
            for(int j=0;j<5;j++) ha[j]=h*c_AT[s][j];

            // ---- Z build: y(regs) + sum ha_j*k_j (bf16 SMEM) -> Zs tf32 ----
            {
                float z[8];
#pragma unroll
                for(int i=0;i<8;i++) z[i]=yreg[i];
                for(int j=0;j<s;j++){
                    float a=ha[j];
                    uint4 kk=*(const uint4*)(ksm + j*4096 + zr*128 + zc);
                    z[0]+=a*__uint_as_float(kk.x<<16);
                    z[1]+=a*__uint_as_float(kk.x&0xFFFF0000u);
                    z[2]+=a*__uint_as_float(kk.y<<16);
                    z[3]+=a*__uint_as_float(kk.y&0xFFFF0000u);
                    z[4]+=a*__uint_as_float(kk.z<<16);
                    z[5]+=a*__uint_as_float(kk.z&0xFFFF0000u);
                    z[6]+=a*__uint_as_float(kk.w<<16);
                    z[7]+=a*__uint_as_float(kk.w&0xFFFF0000u);}
                float* zd=Zs+zr*132+zc;
                *(float4*)zd    =make_float4(f2tf32(z[0]),f2tf32(z[1]),f2tf32(z[2]),f2tf32(z[3]));
                *(float4*)(zd+4)=make_float4(f2tf32(z[4]),f2tf32(z[5]),f2tf32(z[6]),f2tf32(z[7]));
            }
            __syncthreads();

            // ---- G1: H1 = tanh(Z @ w1^T + b1)  tf32 ----
            {
                float acc[2][4]={{0,0,0,0},{0,0,0,0}};
                mmaT16(Zs,132,sm+O_W1,132,acc,wm,wn,ks2*64,lane);
                if(ks2==1){
                    int r0=wm+gid, c=wn+2*tig;
                    *(float2*)(pt+r0*68+c)      =make_float2(acc[0][0],acc[0][1]);
                    *(float2*)(pt+(r0+8)*68+c)  =make_float2(acc[0][2],acc[0][3]);
                    *(float2*)(pt+r0*68+c+8)    =make_float2(acc[1][0],acc[1][1]);
                    *(float2*)(pt+(r0+8)*68+c+8)=make_float2(acc[1][2],acc[1][3]);}
                __syncthreads();
                if(ks2==0){
                    int r0=wm+gid, c=wn+2*tig;
#pragma unroll
                    for(int j=0;j<2;j++){
                        float2 p0=*(float2*)(pt+r0*68+c+8*j);
                        float2 p1=*(float2*)(pt+(r0+8)*68+c+8*j);
                        float bb0=b1s[c+8*j], bb1=b1s[c+8*j+1];
                        int cl=c+8*j, cgl=n0h+cl;
                        unsigned u0=pack_bf2(ftanh(acc[j][0]+p0.x+bb0),ftanh(acc[j][1]+p0.y+bb1));
                        unsigned u1=pack_bf2(ftanh(acc[j][2]+p1.x+bb0),ftanh(acc[j][3]+p1.y+bb1));
                        __stcg((unsigned*)(g_h1+(size_t)(m0+r0)*WW+cgl),u0);
                        __stcg((unsigned*)(g_h1+(size_t)(m0+r0+8)*WW+cgl),u1);
                        *(unsigned*)(h1o+r0*72+cl)    =u0;
                        *(unsigned*)(h1o+(r0+8)*72+cl)=u1;}}
            }
            __syncthreads();   // h1o visible to all warps
            carr();

            // ---- G2 shadow: own-slice contribution (all SMEM, K=64) ----
            float acc2[2][4]={{0,0,0,0},{0,0,0,0}};
            mmaB16(h1o,72,w2h,520,acc2,wm,wn,ks2*32,n0h+ks2*32,lane,2);
            cwait();           // peers' H1 visible

            // ---- G2 remote: 7 groups of 64 cols via 6 cp.async buffers ----
            {
#pragma unroll
                for(int i=0;i<6;i++){
                    if(tid<256) cpa(sgb[i], g_h1+(size_t)(m0+gr)*WW+gl[i]*64+gc);
                    cpc();}
#pragma unroll
                for(int i=0;i<7;i++){
                    waitg(i);
                    __syncthreads();
                    if(i==1){
                        if(tid<256) cpa(sgb[0], g_h1+(size_t)(m0+gr)*WW+gl[6]*64+gc);
                        cpc();}
                    mmaB16(sg+(i%6)*(32*72),72,w2h,520,acc2,wm,wn,
                           ks2*32,gl[i]*64+ks2*32,lane,2);}
                __syncthreads();
                if(ks2==1){
                    int r0=wm+gid, c=wn+2*tig;
                    *(float2*)(pt+r0*68+c)      =make_float2(acc2[0][0],acc2[0][1]);
                    *(float2*)(pt+(r0+8)*68+c)  =make_float2(acc2[0][2],acc2[0][3]);
                    *(float2*)(pt+r0*68+c+8)    =make_float2(acc2[1][0],acc2[1][1]);
                    *(float2*)(pt+(r0+8)*68+c+8)=make_float2(acc2[1][2],acc2[1][3]);}
                __syncthreads();
                if(ks2==0){
                    int r0=wm+gid, c=wn+2*tig;
#pragma unroll
                    for(int j=0;j<2;j++){
                        float2 p0=*(float2*)(pt+r0*68+c+8*j);
                        float2 p1=*(float2*)(pt+(r0+8)*68+c+8*j);
                        float bb0=b2s[c+8*j], bb1=b2s[c+8*j+1];
                        int cl=c+8*j, cgl=n0h+cl;
                        unsigned u0=pack_bf2(ftanh(acc2[j][0]+p0.x+bb0),ftanh(acc2[j][1]+p0.y+bb1));
                        unsigned u1=pack_bf2(ftanh(acc2[j][2]+p1.x+bb0),ftanh(acc2[j][3]+p1.y+bb1));
                        __stcg((unsigned*)(g_h2+(size_t)(m0+r0)*WW+cgl),u0);
                        __stcg((unsigned*)(g_h2+(size_t)(m0+r0+8)*WW+cgl),u1);
                        *(unsigned*)(h2o+r0*72+cl)    =u0;
                        *(unsigned*)(h2o+(r0+8)*72+cl)=u1;}}
            }
            __syncthreads();   // h2o visible
            carr();            // split-phase: release H2 early

            // ---- G3 shadow: Z @ A^T (tf32) + own-slice H2 @ w3^T ----
            float acc3[4]={0,0,0,0};
            mmaT8(Zs,132,sm+O_AM,132,acc3,wm,wn8,ks4*32,lane);
            mmaB8(h2o,72,w3h,520,acc3,wm,wn8,ks4*16,n0h+ks4*16,lane,1);
            cwait();           // peers' H2 visible

            // ---- G3 remote: 7 groups of 64 cols ----
            {
                float2 yo0, yo1;
                if(s==5 && ks4==0){
                    yo0=__ldcg((const float2*)(g_y+(size_t)r0g*DD+cg));
                    yo1=__ldcg((const float2*)(g_y+(size_t)(r0g+8)*DD+cg));}
#pragma unroll
                for(int i=0;i<6;i++){
                    if(tid<256) cpa(sgb[i], g_h2+(size_t)(m0+gr)*WW+gl[i]*64+gc);
                    cpc();}
#pragma unroll
                for(int i=0;i<7;i++){
                    waitg(i);
                    __syncthreads();
                    if(i==1){
                        if(tid<256) cpa(sgb[0], g_h2+(size_t)(m0+gr)*WW+gl[6]*64+gc);
                        cpc();}
                    mmaB8(sg+(i%6)*(32*72),72,w3h,520,acc3,wm,wn8,
                          ks4*16,gl[i]*64+ks4*16,lane,1);}
                __syncthreads();
                if(ks4>0){
                    float* pr=pt+(ks4-1)*512;
                    int r0=wm+gid, c=wn8+2*tig;
                    *(float2*)(pr+r0*16+c)    =make_float2(acc3[0],acc3[1]);
                    *(float2*)(pr+(r0+8)*16+c)=make_float2(acc3[2],acc3[3]);}
                __syncthreads();
                if(ks4==0){
                    int r0=wm+gid, c=wn8+2*tig;
#pragma unroll
                    for(int p=0;p<3;p++){
                        float* pr=pt+p*512;
                        float2 q0=*(float2*)(pr+r0*16+c);
                        float2 q1=*(float2*)(pr+(r0+8)*16+c);
                        acc3[0]+=q0.x; acc3[1]+=q0.y; acc3[2]+=q1.x; acc3[3]+=q1.y;}
                    float bb0=b3s[cg-n0k], bb1=b3s[cg-n0k+1];
                    float kv[4];
                    kv[0]=acc3[0]+bb0; kv[1]=acc3[1]+bb1;
                    kv[2]=acc3[2]+bb0; kv[3]=acc3[3]+bb1;
                    if(s<5){
                        float bs=c_BT[s];
#pragma unroll
                        for(int i=0;i<4;i++) yacc[i]+=bs*kv[i];
#pragma unroll
                        for(int e=0;e<2;e++){
                            int lr=wm+gid+e*8;
                            unsigned kp=pack_bf2(kv[2*e],kv[2*e+1]);
                            uint32_t la=ks_sma + (uint32_t)((s<<12)+lr*128+cg)*2u;
#pragma unroll
                            for(unsigned rr=0;rr<8;rr++) stclu(la,rr,kp);}
                    }else{
                        float b5=c_BT[5];
                        float y0=yo0.x+h*(yacc[0]+b5*kv[0]);
                        float y1=yo0.y+h*(yacc[1]+b5*kv[1]);
                        float y2=yo1.x+h*(yacc[2]+b5*kv[2]);
                        float y3=yo1.y+h*(yacc[3]+b5*kv[3]);
                        __stcg((float2*)(g_y+(size_t)r0g*DD+cg),make_float2(y0,y1));
                        __stcg((float2*)(g_y+(size_t)(r0g+8)*DD+cg),make_float2(y2,y3));
                        *(float2*)(out+(size_t)r0g*TT*DD+(size_t)(t+1)*DD+cg)
                            =make_float2(y0,y1);
                        *(float2*)(out+(size_t)(r0g+8)*TT*DD+(size_t)(t+1)*DD+cg)
                            =make_float2(y2,y3);}}
            }
            carr(); cwait();   // end of stage: k visibility + buffer WAR
        }
    }
    carr(); cwait();
}

extern "C" void kernel_launch(void* const* d_in,const int* in_sizes,int n_in,
                              void* d_out,int out_size){
    (void)in_sizes;(void)n_in;(void)out_size;
    cudaFuncSetAttribute(ode_kernel,cudaFuncAttributeMaxDynamicSharedMemorySize,SMF*4);
    cudaLaunchConfig_t cfg={};
    cfg.gridDim=dim3(128,1,1);
    cfg.blockDim=dim3(NTHR,1,1);
    cfg.dynamicSmemBytes=SMF*4;
    cudaLaunchAttribute at[1];
    at[0].id=cudaLaunchAttributeClusterDimension;
    at[0].val.clusterDim.x=8; at[0].val.clusterDim.y=1; at[0].val.clusterDim.z=1;
    cfg.attrs=at; cfg.numAttrs=1;
    cudaLaunchKernelEx(&cfg,ode_kernel,
        (const float*)d_in[0],(const float*)d_in[1],(const float*)d_in[2],
        (const float*)d_in[3],(const float*)d_in[4],(const float*)d_in[5],
        (const float*)d_in[6],(const float*)d_in[7],(const float*)d_in[8],
        (float*)d_out);
}

// round 16
// speedup vs baseline: 1.1403x; 1.1403x over previous
#include <cuda_runtime.h>
#include <cuda_bf16.h>
#include <cstdint>

#define NB 512
#define DD 128
#define WW 512
#define TT 512
#define NTHR 512

// float-indexed SMEM layout (R6 layout, O_MB removed)
#define O_W1 0                         // 64x132 f32 (tf32)   8448
#define O_AM (O_W1+64*132)             // 16x132 f32          2112
#define O_Z  (O_AM+16*132)             // 32x132 f32          4224
#define O_B  (O_Z+4224)                // 144 biases
#define O_TS (O_B+144)                 // 512 ts
#define O_KS (O_TS+512)                // 5 x (32x128) bf16 = 10240 f
#define O_W2H (O_KS+10240)             // bf16 64x520 = 16640 f
#define O_W3H (O_W2H+16640)            // bf16 16x520 = 4160 f
#define O_SG  (O_W3H+4160)             // 4 x (32x136) bf16 = 8704 f; pt aliases sg[3]
#define SGF   2176
#define SMF   (O_SG+8704)              // 55200 f = 220800 B

__device__ __align__(16) __nv_bfloat16 g_h1[NB*WW];
__device__ __align__(16) __nv_bfloat16 g_h2[NB*WW];
__device__ __align__(16) float g_y[NB*DD];

__constant__ float c_AT[6][5] = {
    {0.f,0.f,0.f,0.f,0.f},
    {0.161f,0.f,0.f,0.f,0.f},
    {-0.008480655492356989f,0.335480655492357f,0.f,0.f,0.f},
    {2.8971530571054935f,-6.359448489975075f,4.3622954328695815f,0.f,0.f},
    {5.325864828439257f,-11.748883564062828f,7.4955393428898365f,-0.09249506636175525f,0.f},
    {5.86145544294642f,-12.92096931784711f,8.159367898576159f,-0.071584973281401f,-0.028269050394068383f}};
__constant__ float c_BT[6] = {0.09646076681806523f,0.01f,0.4798896504144996f,
                              1.379008574103742f,-3.290069515436081f,2.324710524099774f};

__device__ __forceinline__ float f2tf32(float x){
    unsigned u; asm("cvt.rna.tf32.f32 %0,%1;":"=r"(u):"f"(x)); return __uint_as_float(u);}
__device__ __forceinline__ float ftanh(float x){
    float e = exp2f(2.885390081777927f * x);
    return 1.0f - __fdividef(2.0f, e + 1.0f);}
__device__ __forceinline__ unsigned pack_bf2(float lo,float hi){
    unsigned r; asm("cvt.rn.bf16x2.f32 %0,%1,%2;":"=r"(r):"f"(hi),"f"(lo)); return r;}
__device__ __forceinline__ void mma8(float* c,const unsigned* a,const unsigned* b){
    asm volatile("mma.sync.aligned.m16n8k8.row.col.f32.tf32.tf32.f32 "
        "{%0,%1,%2,%3},{%4,%5,%6,%7},{%8,%9},{%0,%1,%2,%3};"
        :"+f"(c[0]),"+f"(c[1]),"+f"(c[2]),"+f"(c[3])
        :"r"(a[0]),"r"(a[1]),"r"(a[2]),"r"(a[3]),"r"(b[0]),"r"(b[1]));}
__device__ __forceinline__ void mmab(float* c,const unsigned* a,const unsigned* b){
    asm volatile("mma.sync.aligned.m16n8k16.row.col.f32.bf16.bf16.f32 "
        "{%0,%1,%2,%3},{%4,%5,%6,%7},{%8,%9},{%0,%1,%2,%3};"
        :"+f"(c[0]),"+f"(c[1]),"+f"(c[2]),"+f"(c[3])
        :"r"(a[0]),"r"(a[1]),"r"(a[2]),"r"(a[3]),"r"(b[0]),"r"(b[1]));}
__device__ __forceinline__ unsigned sma(const void* p){
    return (unsigned)__cvta_generic_to_shared(p);}
__device__ __forceinline__ void ldsm4(unsigned r[4], const void* p){
    asm volatile("ldmatrix.sync.aligned.m8n8.x4.shared.b16 {%0,%1,%2,%3},[%4];"
        :"=r"(r[0]),"=r"(r[1]),"=r"(r[2]),"=r"(r[3]):"r"(sma(p)));}
__device__ __forceinline__ void ldsm2(unsigned r[2], const void* p){
    asm volatile("ldmatrix.sync.aligned.m8n8.x2.shared.b16 {%0,%1},[%2];"
        :"=r"(r[0]),"=r"(r[1]):"r"(sma(p)));}
__device__ __forceinline__ void cpa(uint32_t d,const void* s){
    asm volatile("cp.async.cg.shared.global [%0],[%1],16;"::"r"(d),"l"(s):"memory");}
__device__ __forceinline__ void cpc(){asm volatile("cp.async.commit_group;":::"memory");}
__device__ __forceinline__ void carr(){
    asm volatile("barrier.cluster.arrive.aligned;":::"memory");}
__device__ __forceinline__ void cwait(){
    asm volatile("barrier.cluster.wait.aligned;":::"memory");}
__device__ __forceinline__ void stclu(uint32_t laddr,unsigned rr,unsigned v){
    uint32_t ra;
    asm volatile("mapa.shared::cluster.u32 %0,%1,%2;":"=r"(ra):"r"(laddr),"r"(rr));
    asm volatile("st.shared::cluster.u32 [%0],%1;"::"r"(ra),"r"(v):"memory");}

// ---- G1: tf32 m16n8, full K=128, dual accumulator ----
__device__ __forceinline__ void mmaT8_K128(const float* A,int lda,const float* B,int ldb,
        float acc[4],int wm,int wn8,int lane){
    const float* ap = A + (wm+(lane&15))*lda + ((lane>>4)<<2);
    const float* bp = B + (wn8+(lane&7))*ldb + (((lane>>3)&1)<<2);
    float e[4]={0,0,0,0}, o[4]={0,0,0,0};
#pragma unroll
    for(int kk=0;kk<128;kk+=16){
        unsigned a0[4],b0[2],a1[4],b1v[2];
        ldsm4(a0,ap+kk);   ldsm2(b0,bp+kk);   mma8(e,a0,b0);
        ldsm4(a1,ap+kk+8); ldsm2(b1v,bp+kk+8); mma8(o,a1,b1v);}
#pragma unroll
    for(int i=0;i<4;i++) acc[i]=e[i]+o[i];}

// ---- G2: bf16 m16n8, one 128-col chunk (8 k16 steps), dual accumulator ----
__device__ __forceinline__ void mmaB8_c128(const __nv_bfloat16* A,int lda,
        const __nv_bfloat16* B,int ldb,float e[4],float o[4],int wm,int wn8,
        int koffB,int lane){
    const __nv_bfloat16* ap = A + (wm+(lane&15))*lda + ((lane>>4)<<3);
    const __nv_bfloat16* bp = B + (wn8+(lane&7))*ldb + (((lane>>3)&1)<<3) + koffB;
#pragma unroll
    for(int s=0;s<8;s+=2){
        unsigned a0[4],b0[2],a1[4],b1v[2];
        ldsm4(a0,ap+s*16);    ldsm2(b0,bp+s*16);    mmab(e,a0,b0);
        ldsm4(a1,ap+s*16+16); ldsm2(b1v,bp+s*16+16); mmab(o,a1,b1v);}}

// ---- G3 helpers (unchanged from R6) ----
__device__ __forceinline__ void mmaT8(const float* A,int lda,const float* B,int ldb,
        float acc[4],int wm,int wn8,int koff,int lane){
    const float* ap = A + (wm+(lane&15))*lda + ((lane>>4)<<2) + koff;
    const float* bp = B + (wn8+(lane&7))*ldb + (((lane>>3)&1)<<2) + koff;
#pragma unroll
    for(int kk=0;kk<32;kk+=8){ unsigned a[4],b[2];
        ldsm4(a,ap+kk); ldsm2(b,bp+kk);
        mma8(acc,a,b);}}
__device__ __forceinline__ void mmaB8(const __nv_bfloat16* A,int lda,
        const __nv_bfloat16* B,int ldb,float acc[4],int wm,int wn8,
        int koffA,int koffB,int lane,int nk){
    const __nv_bfloat16* ap = A + (wm+(lane&15))*lda + ((lane>>4)<<3) + koffA;
    const __nv_bfloat16* bp = B + (wn8+(lane&7))*ldb + (((lane>>3)&1)<<3) + koffB;
#pragma unroll
    for(int s=0;s<nk;s++){ unsigned a[4],b[2];
        ldsm4(a,ap+s*16); ldsm2(b,bp+s*16);
        mmab(acc,a,b);}}

__global__ void __launch_bounds__(NTHR,1) ode_kernel(
        const float* __restrict__ ts,const float* __restrict__ yi,
        const float* __restrict__ w1,const float* __restrict__ b1,
        const float* __restrict__ w2,const float* __restrict__ b2,
        const float* __restrict__ w3,const float* __restrict__ b3,
        const float* __restrict__ Am,float* __restrict__ out){
    extern __shared__ float sm[];
    __nv_bfloat16* w2h=(__nv_bfloat16*)(sm+O_W2H);
    __nv_bfloat16* w3h=(__nv_bfloat16*)(sm+O_W3H);
    __nv_bfloat16* ksm=(__nv_bfloat16*)(sm+O_KS);
    __nv_bfloat16* sg =(__nv_bfloat16*)(sm+O_SG);
    float* Zs=sm+O_Z;
    float* pt=sm+O_SG+3*SGF;           // aliased onto sg[3]; used only by G3
    const float* tss=sm+O_TS;

    const int tid=threadIdx.x, wid=tid>>5, lane=tid&31;
    const int gid=lane>>2, tig=lane&3;
    const int wm=(wid&1)*16;
    const int wn8g=(wid>>1)*8;                 // G1/G2: 2M x 8N, full K
    const int wn8=((wid>>1)&1)*8, ks4=wid>>2;  // G3: 2M x 2N x 4K-split
    const int rank=blockIdx.x&7, clus=blockIdx.x>>3;
    const int m0=clus*32, n0h=rank*64, n0k=rank*16;
    const uint32_t ks_sma=sma(ksm);

    const int sr=tid>>4, sc=(tid&15)<<3;
    uint32_t sgb[4];
#pragma unroll
    for(int i=0;i<4;i++) sgb[i]=sma(sg+i*(32*136)) + (uint32_t)(sr*136+sc)*2u;

    // ---- init ----
    for(int i=tid;i<64*512;i+=NTHR){int n=i>>9,k=i&511;
        w2h[n*520+k]=__float2bfloat16(w2[(size_t)(n0h+n)*WW+k]);}
    for(int i=tid;i<16*512;i+=NTHR){int n=i>>9,k=i&511;
        w3h[n*520+k]=__float2bfloat16(w3[(size_t)(n0k+n)*WW+k]);}
    for(int i=tid;i<64*128;i+=NTHR){int n=i>>7,k=i&127;
        sm[O_W1+n*132+k]=f2tf32(w1[(size_t)(n0h+n)*DD+k]);}
    for(int i=tid;i<16*128;i+=NTHR){int n=i>>7,k=i&127;
        sm[O_AM+n*132+k]=f2tf32(Am[(size_t)(n0k+n)*DD+k]);}
    if(tid<64) sm[O_B+tid]=b1[n0h+tid];
    else if(tid<128) sm[O_B+tid]=b2[n0h+tid-64];
    else if(tid<144) sm[O_B+tid]=b3[n0k+tid-128];
    sm[O_TS+tid]=ts[tid];
    {   int i=rank*NTHR+tid;
        int r=i>>7,c=i&127; float v=yi[(size_t)(m0+r)*DD+c];
        __stcg(g_y+(size_t)(m0+r)*DD+c,v);
        out[(size_t)(m0+r)*TT*DD+c]=v;}
    __syncthreads();
    carr(); cwait();

    const float* b1s=sm+O_B; const float* b2s=sm+O_B+64; const float* b3s=sm+O_B+128;
    const int zr=tid>>4, zc=(tid&15)<<3;
    const int clE=wn8g+2*tig;          // G1/G2 epilogue col (0..63)
    const int cg=n0k+wn8+2*tig;        // G3 epilogue col (global)
    const int r0g=m0+wm+gid;

    float yreg[8];

    for(int t=0;t<TT-1;t++){
        const float h=tss[t+1]-tss[t];
        float yacc[4]={0.f,0.f,0.f,0.f};
        {   const float4* yp=(const float4*)(g_y+(size_t)(m0+zr)*DD+zc);
            float4 a=__ldcg(yp), b=__ldcg(yp+1);
            yreg[0]=a.x;yreg[1]=a.y;yreg[2]=a.z;yreg[3]=a.w;
            yreg[4]=b.x;yreg[5]=b.y;yreg[6]=b.z;yreg[7]=b.w;}
        for(int s=0;s<6;s++){
            float ha[5];
#pragma unroll
            for(int j=0;j<5;j++) ha[j]=h*c_AT[s][j];

            // ---- Z build: y (regs) + sum ha_j * k_j (bf16 SMEM) -> Zs tf32 ----
            {
                float z[8];
#pragma unroll
                for(int i=0;i<8;i++) z[i]=yreg[i];
                for(int j=0;j<s;j++){
                    float a=ha[j];
                    uint4 kk=*(const uint4*)(ksm + j*4096 + zr*128 + zc);
                    z[0]+=a*__uint_as_float(kk.x<<16);
                    z[1]+=a*__uint_as_float(kk.x&0xFFFF0000u);
                    z[2]+=a*__uint_as_float(kk.y<<16);
                    z[3]+=a*__uint_as_float(kk.y&0xFFFF0000u);
                    z[4]+=a*__uint_as_float(kk.z<<16);
                    z[5]+=a*__uint_as_float(kk.z&0xFFFF0000u);
                    z[6]+=a*__uint_as_float(kk.w<<16);
                    z[7]+=a*__uint_as_float(kk.w&0xFFFF0000u);}
                float* zd=Zs+zr*132+zc;
                *(float4*)zd    =make_float4(f2tf32(z[0]),f2tf32(z[1]),f2tf32(z[2]),f2tf32(z[3]));
                *(float4*)(zd+4)=make_float4(f2tf32(z[4]),f2tf32(z[5]),f2tf32(z[6]),f2tf32(z[7]));
            }
            __syncthreads();

            // ---- G1: H1 = tanh(Z @ w1^T + b1)  tf32, m16n8 full-K, no K-split ----
            {
                float acc[4];
                mmaT8_K128(Zs,132,sm+O_W1,132,acc,wm,wn8g,lane);
                float bb0=b1s[clE], bb1=b1s[clE+1];
                int cgl=n0h+clE;
                unsigned u0=pack_bf2(ftanh(acc[0]+bb0),ftanh(acc[1]+bb1));
                unsigned u1=pack_bf2(ftanh(acc[2]+bb0),ftanh(acc[3]+bb1));
                __stcg((unsigned*)(g_h1+(size_t)r0g*WW+cgl),u0);
                __stcg((unsigned*)(g_h1+(size_t)(r0g+8)*WW+cgl),u1);
            }
            carr(); cwait();   // H1 exchange

            // ---- G2: H2 = tanh(H1 @ w2^T + b2)  bf16, full prefetch, no K-split ----
            {
#pragma unroll
                for(int ck=0;ck<4;ck++){
                    cpa(sgb[ck], g_h1+(size_t)(m0+sr)*WW+ck*128+sc); cpc();}
                float e[4]={0,0,0,0}, o[4]={0,0,0,0};
#pragma unroll
                for(int ck=0;ck<4;ck++){
                    if(ck==0)      asm volatile("cp.async.wait_group 3;":::"memory");
                    else if(ck==1) asm volatile("cp.async.wait_group 2;":::"memory");
                    else if(ck==2) asm volatile("cp.async.wait_group 1;":::"memory");
                    else           asm volatile("cp.async.wait_group 0;":::"memory");
                    __syncthreads();
                    mmaB8_c128(sg+ck*(32*136),136,w2h,520,e,o,wm,wn8g,ck*128,lane);}
                __syncthreads();   // all warps done reading sg before G3 reuses it
                float bb0=b2s[clE], bb1=b2s[clE+1];
                int cgl=n0h+clE;
                unsigned u0=pack_bf2(ftanh(e[0]+o[0]+bb0),ftanh(e[1]+o[1]+bb1));
                unsigned u1=pack_bf2(ftanh(e[2]+o[2]+bb0),ftanh(e[3]+o[3]+bb1));
                __stcg((unsigned*)(g_h2+(size_t)r0g*WW+cgl),u0);
                __stcg((unsigned*)(g_h2+(size_t)(r0g+8)*WW+cgl),u1);
            }
            carr();                       // split-phase: release H2 early

            // ---- G3 local part while peers catch up: Z @ A^T (tf32) ----
            float acc3[4]={0,0,0,0};
            mmaT8(Zs,132,sm+O_AM,132,acc3,wm,wn8,ks4*32,lane);
            cwait();                      // peers' H2 now visible

            // ---- G3: += H2 @ w3^T  (bf16, K-split4 + pt reduction) ----
            {
#pragma unroll
                for(int ck=0;ck<4;ck++){
                    cpa(sgb[ck], g_h2+(size_t)(m0+sr)*WW+ck*128+sc); cpc();}
                float2 yo0, yo1;
                if(s==5 && ks4==0){
                    yo0=__ldcg((const float2*)(g_y+(size_t)r0g*DD+cg));
                    yo1=__ldcg((const float2*)(g_y+(size_t)(r0g+8)*DD+cg));}
#pragma unroll
                for(int ck=0;ck<4;ck++){
                    if(ck==0)      asm volatile("cp.async.wait_group 3;":::"memory");
                    else if(ck==1) asm volatile("cp.async.wait_group 2;":::"memory");
                    else if(ck==2) asm volatile("cp.async.wait_group 1;":::"memory");
                    else           asm volatile("cp.async.wait_group 0;":::"memory");
                    __syncthreads();
                    mmaB8(sg+ck*(32*136),136,w3h,520,acc3,wm,wn8,ks4*32,ck*128+ks4*32,lane,2);}
                __syncthreads();   // protect sg[3] (=pt)
                if(ks4>0){
                    float* pr=pt+(ks4-1)*512;
                    int r0=wm+gid, c=wn8+2*tig;
                    *(float2*)(pr+r0*16+c)    =make_float2(acc3[0],acc3[1]);
                    *(float2*)(pr+(r0+8)*16+c)=make_float2(acc3[2],acc3[3]);}
                __syncthreads();
                if(ks4==0){
                    int r0=wm+gid, c=wn8+2*tig;
#pragma unroll
                    for(int p=0;p<3;p++){
                        float* pr=pt+p*512;
                        float2 q0=*(float2*)(pr+r0*16+c);
                        float2 q1=*(float2*)(pr+(r0+8)*16+c);
                        acc3[0]+=q0.x; acc3[1]+=q0.y; acc3[2]+=q1.x; acc3[3]+=q1.y;}
                    float bb0=b3s[cg-n0k], bb1=b3s[cg-n0k+1];
                    float kv[4];
                    kv[0]=acc3[0]+bb0; kv[1]=acc3[1]+bb1;
                    kv[2]=acc3[2]+bb0; kv[3]=acc3[3]+bb1;
                    if(s<5){
                        float bs=c_BT[s];
#pragma unroll
                        for(int i=0;i<4;i++) yacc[i]+=bs*kv[i];
#pragma unroll
                        for(int e2=0;e2<2;e2++){
                            int lr=wm+gid+e2*8;
                            unsigned kp=pack_bf2(kv[2*e2],kv[2*e2+1]);
                            uint32_t la=ks_sma + (uint32_t)((s<<12)+lr*128+cg)*2u;
#pragma unroll
                            for(unsigned rr=0;rr<8;rr++) stclu(la,rr,kp);}
                    }else{
                        float b5=c_BT[5];
                        float y0=yo0.x+h*(yacc[0]+b5*kv[0]);
                        float y1=yo0.y+h*(yacc[1]+b5*kv[1]);
                        float y2=yo1.x+h*(yacc[2]+b5*kv[2]);
                        float y3=yo1.y+h*(yacc[3]+b5*kv[3]);
                        __stcg((float2*)(g_y+(size_t)r0g*DD+cg),make_float2(y0,y1));
                        __stcg((float2*)(g_y+(size_t)(r0g+8)*DD+cg),make_float2(y2,y3));
                        *(float2*)(out+(size_t)r0g*TT*DD+(size_t)(t+1)*DD+cg)
                            =make_float2(y0,y1);
                        *(float2*)(out+(size_t)(r0g+8)*TT*DD+(size_t)(t+1)*DD+cg)
                            =make_float2(y2,y3);}}
            }
            carr(); cwait();   // end of stage: k visibility + buffer WAR
        }
    }
    carr(); cwait();   // no CTA exits while peers' remote SMEM stores are in flight
}

extern "C" void kernel_launch(void* const* d_in,const int* in_sizes,int n_in,
                              void* d_out,int out_size){
    (void)in_sizes;(void)n_in;(void)out_size;
    cudaFuncSetAttribute(ode_kernel,cudaFuncAttributeMaxDynamicSharedMemorySize,SMF*4);
    cudaLaunchConfig_t cfg={};
    cfg.gridDim=dim3(128,1,1);
    cfg.blockDim=dim3(NTHR,1,1);
    cfg.dynamicSmemBytes=SMF*4;
    cudaLaunchAttribute at[1];
    at[0].id=cudaLaunchAttributeClusterDimension;
    at[0].val.clusterDim.x=8; at[0].val.clusterDim.y=1; at[0].val.clusterDim.z=1;
    cfg.attrs=at; cfg.numAttrs=1;
    cudaLaunchKernelEx(&cfg,ode_kernel,
        (const float*)d_in[0],(const float*)d_in[1],(const float*)d_in[2],
        (const float*)d_in[3],(const float*)d_in[4],(const float*)d_in[5],
        (const float*)d_in[6],(const float*)d_in[7],(const float*)d_in[8],
        (float*)d_out);
}

// round 17
// speedup vs baseline: 1.2719x; 1.1155x over previous
#include <cuda_runtime.h>
#include <cuda_bf16.h>
#include <cstdint>

#define NB 512
#define DD 128
#define WW 512
#define TT 512
#define NTHR 512

// float-indexed SMEM layout
#define O_W1 0                         // 64x132 f32 (tf32)      8448
#define O_AM (O_W1+64*132)             // 16x132 f32             2112
#define O_Z  (O_AM+16*132)             // 32x132 f32             4224
#define O_B  (O_Z+4224)                // 144 biases
#define O_TS (O_B+144)                 // 512 ts
#define O_KS (O_TS+512)                // 5 x (32x128) bf16 = 10240 f
#define O_W2H (O_KS+10240)             // bf16 64x520 = 16640 f
#define O_W3H (O_W2H+16640)            // bf16 16x520 = 4160 f
#define O_SG  (O_W3H+4160)             // 4 x (32x136) bf16 = 8704 f; pt aliases sg[3]
#define SGF   2176
#define SMF   (O_SG+8704)              // 55200 f = 220800 B

__device__ __align__(16) __nv_bfloat16 g_h1[NB*WW];
__device__ __align__(16) __nv_bfloat16 g_h2[NB*WW];
__device__ __align__(16) float g_y[NB*DD];

__constant__ float c_AT[6][5] = {
    {0.f,0.f,0.f,0.f,0.f},
    {0.161f,0.f,0.f,0.f,0.f},
    {-0.008480655492356989f,0.335480655492357f,0.f,0.f,0.f},
    {2.8971530571054935f,-6.359448489975075f,4.3622954328695815f,0.f,0.f},
    {5.325864828439257f,-11.748883564062828f,7.4955393428898365f,-0.09249506636175525f,0.f},
    {5.86145544294642f,-12.92096931784711f,8.159367898576159f,-0.071584973281401f,-0.028269050394068383f}};
__constant__ float c_BT[6] = {0.09646076681806523f,0.01f,0.4798896504144996f,
                              1.379008574103742f,-3.290069515436081f,2.324710524099774f};

__device__ __forceinline__ float f2tf32(float x){
    unsigned u; asm("cvt.rna.tf32.f32 %0,%1;":"=r"(u):"f"(x)); return __uint_as_float(u);}
__device__ __forceinline__ float ftanh(float x){
    float r; asm("tanh.approx.f32 %0,%1;":"=f"(r):"f"(x)); return r;}
__device__ __forceinline__ unsigned pack_bf2(float lo,float hi){
    unsigned r; asm("cvt.rn.bf16x2.f32 %0,%1,%2;":"=r"(r):"f"(hi),"f"(lo)); return r;}
__device__ __forceinline__ void mma8(float* c,const unsigned* a,const unsigned* b){
    asm volatile("mma.sync.aligned.m16n8k8.row.col.f32.tf32.tf32.f32 "
        "{%0,%1,%2,%3},{%4,%5,%6,%7},{%8,%9},{%0,%1,%2,%3};"
        :"+f"(c[0]),"+f"(c[1]),"+f"(c[2]),"+f"(c[3])
        :"r"(a[0]),"r"(a[1]),"r"(a[2]),"r"(a[3]),"r"(b[0]),"r"(b[1]));}
__device__ __forceinline__ void mmab(float* c,const unsigned* a,const unsigned* b){
    asm volatile("mma.sync.aligned.m16n8k16.row.col.f32.bf16.bf16.f32 "
        "{%0,%1,%2,%3},{%4,%5,%6,%7},{%8,%9},{%0,%1,%2,%3};"
        :"+f"(c[0]),"+f"(c[1]),"+f"(c[2]),"+f"(c[3])
        :"r"(a[0]),"r"(a[1]),"r"(a[2]),"r"(a[3]),"r"(b[0]),"r"(b[1]));}
__device__ __forceinline__ unsigned sma(const void* p){
    return (unsigned)__cvta_generic_to_shared(p);}
__device__ __forceinline__ void ldsm4(unsigned r[4], const void* p){
    asm volatile("ldmatrix.sync.aligned.m8n8.x4.shared.b16 {%0,%1,%2,%3},[%4];"
        :"=r"(r[0]),"=r"(r[1]),"=r"(r[2]),"=r"(r[3]):"r"(sma(p)));}
__device__ __forceinline__ void ldsm2(unsigned r[2], const void* p){
    asm volatile("ldmatrix.sync.aligned.m8n8.x2.shared.b16 {%0,%1},[%2];"
        :"=r"(r[0]),"=r"(r[1]):"r"(sma(p)));}
__device__ __forceinline__ void cpa(uint32_t d,const void* s){
    asm volatile("cp.async.cg.shared.global [%0],[%1],16;"::"r"(d),"l"(s):"memory");}
__device__ __forceinline__ void cpc(){asm volatile("cp.async.commit_group;":::"memory");}
__device__ __forceinline__ void carr(){
    asm volatile("barrier.cluster.arrive.aligned;":::"memory");}
__device__ __forceinline__ void cwait(){
    asm volatile("barrier.cluster.wait.aligned;":::"memory");}
__device__ __forceinline__ void stclu(uint32_t laddr,unsigned rr,unsigned v){
    uint32_t ra;
    asm volatile("mapa.shared::cluster.u32 %0,%1,%2;":"=r"(ra):"r"(laddr),"r"(rr));
    asm volatile("st.shared::cluster.u32 [%0],%1;"::"r"(ra),"r"(v):"memory");}

// tf32 m16n16, 64 K-cols from koff
__device__ __forceinline__ void mmaT16(const float* A,int lda,const float* B,int ldb,
        float acc[2][4],int wm,int wn,int koff,int lane){
    const float* ap = A + (wm+(lane&15))*lda + ((lane>>4)<<2) + koff;
    const float* bp = B + (wn+(lane&7)+((lane>>4)<<3))*ldb + (((lane>>3)&1)<<2) + koff;
#pragma unroll
    for(int kk=0;kk<64;kk+=8){ unsigned a[4],b[4];
        ldsm4(a,ap+kk); ldsm4(b,bp+kk);
        mma8(acc[0],a,b); mma8(acc[1],a,b+2);}}

// tf32 m16n8, 32 K-cols from koff
__device__ __forceinline__ void mmaT8(const float* A,int lda,const float* B,int ldb,
        float acc[4],int wm,int wn8,int koff,int lane){
    const float* ap = A + (wm+(lane&15))*lda + ((lane>>4)<<2) + koff;
    const float* bp = B + (wn8+(lane&7))*ldb + (((lane>>3)&1)<<2) + koff;
#pragma unroll
    for(int kk=0;kk<32;kk+=8){ unsigned a[4],b[2];
        ldsm4(a,ap+kk); ldsm2(b,bp+kk);
        mma8(acc,a,b);}}

// bf16 m16n16, nk k16-steps
__device__ __forceinline__ void mmaB16(const __nv_bfloat16* A,int lda,
        const __nv_bfloat16* B,int ldb,float acc[2][4],int wm,int wn,
        int koffA,int koffB,int lane,int nk){
    const __nv_bfloat16* ap = A + (wm+(lane&15))*lda + ((lane>>4)<<3) + koffA;
    const __nv_bfloat16* bp = B + (wn+(lane&7)+((lane>>4)<<3))*ldb + (((lane>>3)&1)<<3) + koffB;
#pragma unroll
    for(int s=0;s<nk;s++){ unsigned a[4],b[4];
        ldsm4(a,ap+s*16); ldsm4(b,bp+s*16);
        mmab(acc[0],a,b); mmab(acc[1],a,b+2);}}

// bf16 m16n8, nk k16-steps
__device__ __forceinline__ void mmaB8(const __nv_bfloat16* A,int lda,
        const __nv_bfloat16* B,int ldb,float acc[4],int wm,int wn8,
        int koffA,int koffB,int lane,int nk){
    const __nv_bfloat16* ap = A + (wm+(lane&15))*lda + ((lane>>4)<<3) + koffA;
    const __nv_bfloat16* bp = B + (wn8+(lane&7))*ldb + (((lane>>3)&1)<<3) + koffB;
#pragma unroll
    for(int s=0;s<nk;s++){ unsigned a[4],b[2];
        ldsm4(a,ap+s*16); ldsm2(b,bp+s*16);
        mmab(acc,a,b);}}

__global__ void __launch_bounds__(NTHR,1) ode_kernel(
        const float* __restrict__ ts,const float* __restrict__ yi,
        const float* __restrict__ w1,const float* __restrict__ b1,
        const float* __restrict__ w2,const float* __restrict__ b2,
        const float* __restrict__ w3,const float* __restrict__ b3,
        const float* __restrict__ Am,float* __restrict__ out){
    extern __shared__ float sm[];
    __nv_bfloat16* w2h=(__nv_bfloat16*)(sm+O_W2H);
    __nv_bfloat16* w3h=(__nv_bfloat16*)(sm+O_W3H);
    __nv_bfloat16* ksm=(__nv_bfloat16*)(sm+O_KS);
    __nv_bfloat16* sg =(__nv_bfloat16*)(sm+O_SG);
    float* Zs=sm+O_Z;
    float* pt=sm+O_SG+3*SGF;           // aliased onto sg[3]
    const float* tss=sm+O_TS;

    const int tid=threadIdx.x, wid=tid>>5, lane=tid&31;
    const int gid=lane>>2, tig=lane&3;
    const int wm=(wid&1)*16, wn=((wid>>1)&3)*16, ks2=wid>>3;
    const int wn8=((wid>>1)&1)*8, ks4=wid>>2;
    const int rank=blockIdx.x&7, clus=blockIdx.x>>3;
    const int m0=clus*32, n0h=rank*64, n0k=rank*16;
    const uint32_t ks_sma=sma(ksm);

    const int sr=tid>>4, sc=(tid&15)<<3;
    uint32_t sgb[4];
#pragma unroll
    for(int i=0;i<4;i++) sgb[i]=sma(sg+i*(32*136)) + (uint32_t)(sr*136+sc)*2u;

    // ---- init ----
    for(int i=tid;i<64*512;i+=NTHR){int n=i>>9,k=i&511;
        w2h[n*520+k]=__float2bfloat16(w2[(size_t)(n0h+n)*WW+k]);}
    for(int i=tid;i<16*512;i+=NTHR){int n=i>>9,k=i&511;
        w3h[n*520+k]=__float2bfloat16(w3[(size_t)(n0k+n)*WW+k]);}
    for(int i=tid;i<64*128;i+=NTHR){int n=i>>7,k=i&127;
        sm[O_W1+n*132+k]=f2tf32(w1[(size_t)(n0h+n)*DD+k]);}
    for(int i=tid;i<16*128;i+=NTHR){int n=i>>7,k=i&127;
        sm[O_AM+n*132+k]=f2tf32(Am[(size_t)(n0k+n)*DD+k]);}
    if(tid<64) sm[O_B+tid]=b1[n0h+tid];
    else if(tid<128) sm[O_B+tid]=b2[n0h+tid-64];
    else if(tid<144) sm[O_B+tid]=b3[n0k+tid-128];
    sm[O_TS+tid]=ts[tid];
    {   int i=rank*NTHR+tid;
        int r=i>>7,c=i&127; float v=yi[(size_t)(m0+r)*DD+c];
        __stcg(g_y+(size_t)(m0+r)*DD+c,v);
        out[(size_t)(m0+r)*TT*DD+c]=v;}
    __syncthreads();
    carr(); cwait();

    const float* b1s=sm+O_B; const float* b2s=sm+O_B+64; const float* b3s=sm+O_B+128;
    const int zr=tid>>4, zc=(tid&15)<<3;
    const int cg=n0k+wn8+2*tig;
    const int r0g=m0+wm+gid;

    float yreg[8];

    for(int t=0;t<TT-1;t++){
        const float h=tss[t+1]-tss[t];
        float yacc[4]={0.f,0.f,0.f,0.f};
        {   const float4* yp=(const float4*)(g_y+(size_t)(m0+zr)*DD+zc);
            float4 a=__ldcg(yp), b=__ldcg(yp+1);
            yreg[0]=a.x;yreg[1]=a.y;yreg[2]=a.z;yreg[3]=a.w;
            yreg[4]=b.x;yreg[5]=b.y;yreg[6]=b.z;yreg[7]=b.w;}
        for(int s=0;s<6;s++){
            float ha[5];
#pragma unroll
            for(int j=0;j<5;j++) ha[j]=h*c_AT[s][j];

            // ---- Z build: y (regs) + sum ha_j * k_j (bf16 SMEM) -> Zs tf32 ----
            {
                float z[8];
#pragma unroll
                for(int i=0;i<8;i++) z[i]=yreg[i];
                for(int j=0;j<s;j++){
                    float a=ha[j];
                    uint4 kk=*(const uint4*)(ksm + j*4096 + zr*128 + zc);
                    z[0]+=a*__uint_as_float(kk.x<<16);
                    z[1]+=a*__uint_as_float(kk.x&0xFFFF0000u);
                    z[2]+=a*__uint_as_float(kk.y<<16);
                    z[3]+=a*__uint_as_float(kk.y&0xFFFF0000u);
                    z[4]+=a*__uint_as_float(kk.z<<16);
                    z[5]+=a*__uint_as_float(kk.z&0xFFFF0000u);
                    z[6]+=a*__uint_as_float(kk.w<<16);
                    z[7]+=a*__uint_as_float(kk.w&0xFFFF0000u);}
                float* zd=Zs+zr*132+zc;
                *(float4*)zd    =make_float4(f2tf32(z[0]),f2tf32(z[1]),f2tf32(z[2]),f2tf32(z[3]));
                *(float4*)(zd+4)=make_float4(f2tf32(z[4]),f2tf32(z[5]),f2tf32(z[6]),f2tf32(z[7]));
            }
            __syncthreads();

            // ---- G1: H1 = tanh(Z @ w1^T + b1)  tf32 ----
            {
                float acc[2][4]={{0,0,0,0},{0,0,0,0}};
                mmaT16(Zs,132,sm+O_W1,132,acc,wm,wn,ks2*64,lane);
                if(ks2==1){
                    int r0=wm+gid, c=wn+2*tig;
                    *(float2*)(pt+r0*68+c)      =make_float2(acc[0][0],acc[0][1]);
                    *(float2*)(pt+(r0+8)*68+c)  =make_float2(acc[0][2],acc[0][3]);
                    *(float2*)(pt+r0*68+c+8)    =make_float2(acc[1][0],acc[1][1]);
                    *(float2*)(pt+(r0+8)*68+c+8)=make_float2(acc[1][2],acc[1][3]);}
                __syncthreads();
                if(ks2==0){
                    int r0=wm+gid, c=wn+2*tig;
#pragma unroll
                    for(int j=0;j<2;j++){
                        float2 p0=*(float2*)(pt+r0*68+c+8*j);
                        float2 p1=*(float2*)(pt+(r0+8)*68+c+8*j);
                        float bb0=b1s[c+8*j], bb1=b1s[c+8*j+1];
                        int cgl=n0h+c+8*j;
                        unsigned u0=pack_bf2(ftanh(acc[j][0]+p0.x+bb0),ftanh(acc[j][1]+p0.y+bb1));
                        unsigned u1=pack_bf2(ftanh(acc[j][2]+p1.x+bb0),ftanh(acc[j][3]+p1.y+bb1));
                        __stcg((unsigned*)(g_h1+(size_t)(m0+r0)*WW+cgl),u0);
                        __stcg((unsigned*)(g_h1+(size_t)(m0+r0+8)*WW+cgl),u1);}}
            }
            carr(); cwait();   // H1 exchange

            // ---- G2: H2 = tanh(H1 @ w2^T + b2)  bf16, full prefetch ----
            {
#pragma unroll
                for(int ck=0;ck<4;ck++){
                    cpa(sgb[ck], g_h1+(size_t)(m0+sr)*WW+ck*128+sc); cpc();}
                float acc[2][4]={{0,0,0,0},{0,0,0,0}};
#pragma unroll
                for(int ck=0;ck<4;ck++){
                    if(ck==0)      asm volatile("cp.async.wait_group 3;":::"memory");
                    else if(ck==1) asm volatile("cp.async.wait_group 2;":::"memory");
                    else if(ck==2) asm volatile("cp.async.wait_group 1;":::"memory");
                    else           asm volatile("cp.async.wait_group 0;":::"memory");
                    __syncthreads();
                    mmaB16(sg+ck*(32*136),136,w2h,520,acc,wm,wn,ks2*64,ck*128+ks2*64,lane,4);}
                __syncthreads();   // protect sg[3] (=pt) until all reads done
                if(ks2==1){
                    int r0=wm+gid, c=wn+2*tig;
                    *(float2*)(pt+r0*68+c)      =make_float2(acc[0][0],acc[0][1]);
                    *(float2*)(pt+(r0+8)*68+c)  =make_float2(acc[0][2],acc[0][3]);
                    *(float2*)(pt+r0*68+c+8)    =make_float2(acc[1][0],acc[1][1]);
                    *(float2*)(pt+(r0+8)*68+c+8)=make_float2(acc[1][2],acc[1][3]);}
                __syncthreads();
                if(ks2==0){
                    int r0=wm+gid, c=wn+2*tig;
#pragma unroll
                    for(int j=0;j<2;j++){
                        float2 p0=*(float2*)(pt+r0*68+c+8*j);
                        float2 p1=*(float2*)(pt+(r0+8)*68+c+8*j);
                        float bb0=b2s[c+8*j], bb1=b2s[c+8*j+1];
                        int cgl=n0h+c+8*j;
                        unsigned u0=pack_bf2(ftanh(acc[j][0]+p0.x+bb0),ftanh(acc[j][1]+p0.y+bb1));
                        unsigned u1=pack_bf2(ftanh(acc[j][2]+p1.x+bb0),ftanh(acc[j][3]+p1.y+bb1));
                        __stcg((unsigned*)(g_h2+(size_t)(m0+r0)*WW+cgl),u0);
                        __stcg((unsigned*)(g_h2+(size_t)(m0+r0+8)*WW+cgl),u1);}}
            }
            carr();                       // split-phase: release H2 early

            // ---- G3 local part while peers catch up: Z @ A^T (tf32) ----
            float acc3[4]={0,0,0,0};
            mmaT8(Zs,132,sm+O_AM,132,acc3,wm,wn8,ks4*32,lane);
            cwait();                      // peers' H2 now visible

            // ---- G3: += H2 @ w3^T  (bf16) ----
            {
#pragma unroll
                for(int ck=0;ck<4;ck++){
                    cpa(sgb[ck], g_h2+(size_t)(m0+sr)*WW+ck*128+sc); cpc();}
                float2 yo0, yo1;
                if(s==5 && ks4==0){
                    yo0=__ldcg((const float2*)(g_y+(size_t)r0g*DD+cg));
                    yo1=__ldcg((const float2*)(g_y+(size_t)(r0g+8)*DD+cg));}
#pragma unroll
                for(int ck=0;ck<4;ck++){
                    if(ck==0)      asm volatile("cp.async.wait_group 3;":::"memory");
                    else if(ck==1) asm volatile("cp.async.wait_group 2;":::"memory");
                    else if(ck==2) asm volatile("cp.async.wait_group 1;":::"memory");
                    else           asm volatile("cp.async.wait_group 0;":::"memory");
                    __syncthreads();
                    mmaB8(sg+ck*(32*136),136,w3h,520,acc3,wm,wn8,ks4*32,ck*128+ks4*32,lane,2);}
                __syncthreads();   // protect sg[3] (=pt) until all reads done
                if(ks4>0){
                    float* pr=pt+(ks4-1)*512;
                    int r0=wm+gid, c=wn8+2*tig;
                    *(float2*)(pr+r0*16+c)    =make_float2(acc3[0],acc3[1]);
                    *(float2*)(pr+(r0+8)*16+c)=make_float2(acc3[2],acc3[3]);}
                __syncthreads();
                if(ks4==0){
                    int r0=wm+gid, c=wn8+2*tig;
#pragma unroll
                    for(int p=0;p<3;p++){
                        float* pr=pt+p*512;
                        float2 q0=*(float2*)(pr+r0*16+c);
                        float2 q1=*(float2*)(pr+(r0+8)*16+c);
                        acc3[0]+=q0.x; acc3[1]+=q0.y; acc3[2]+=q1.x; acc3[3]+=q1.y;}
                    float bb0=b3s[cg-n0k], bb1=b3s[cg-n0k+1];
                    float kv[4];
                    kv[0]=acc3[0]+bb0; kv[1]=acc3[1]+bb1;
                    kv[2]=acc3[2]+bb0; kv[3]=acc3[3]+bb1;
                    if(s<5){
                        float bs=c_BT[s];
#pragma unroll
                        for(int i=0;i<4;i++) yacc[i]+=bs*kv[i];
#pragma unroll
                        for(int e=0;e<2;e++){
                            int lr=wm+gid+e*8;
                            unsigned kp=pack_bf2(kv[2*e],kv[2*e+1]);
                            uint32_t la=ks_sma + (uint32_t)((s<<12)+lr*128+cg)*2u;
#pragma unroll
                            for(unsigned rr=0;rr<8;rr++) stclu(la,rr,kp);}
                    }else{
                        float b5=c_BT[5];
                        float y0=yo0.x+h*(yacc[0]+b5*kv[0]);
                        float y1=yo0.y+h*(yacc[1]+b5*kv[1]);
                        float y2=yo1.x+h*(yacc[2]+b5*kv[2]);
                        float y3=yo1.y+h*(yacc[3]+b5*kv[3]);
                        __stcg((float2*)(g_y+(size_t)r0g*DD+cg),make_float2(y0,y1));
                        __stcg((float2*)(g_y+(size_t)(r0g+8)*DD+cg),make_float2(y2,y3));
                        *(float2*)(out+(size_t)r0g*TT*DD+(size_t)(t+1)*DD+cg)
                            =make_float2(y0,y1);
                        *(float2*)(out+(size_t)(r0g+8)*TT*DD+(size_t)(t+1)*DD+cg)
                            =make_float2(y2,y3);}}
            }
            carr(); cwait();   // end of stage: k visibility + buffer WAR
        }
    }
    carr(); cwait();   // no CTA exits while peers' remote SMEM stores are in flight
}

extern "C" void kernel_launch(void* const* d_in,const int* in_sizes,int n_in,
                              void* d_out,int out_size){
    (void)in_sizes;(void)n_in;(void)out_size;
    cudaFuncSetAttribute(ode_kernel,cudaFuncAttributeMaxDynamicSharedMemorySize,SMF*4);
    cudaLaunchConfig_t cfg={};
    cfg.gridDim=dim3(128,1,1);
    cfg.blockDim=dim3(NTHR,1,1);
    cfg.dynamicSmemBytes=SMF*4;
    cudaLaunchAttribute at[1];
    at[0].id=cudaLaunchAttributeClusterDimension;
    at[0].val.clusterDim.x=8; at[0].val.clusterDim.y=1; at[0].val.clusterDim.z=1;
    cfg.attrs=at; cfg.numAttrs=1;
    cudaLaunchKernelEx(&cfg,ode_kernel,
        (const float*)d_in[0],(const float*)d_in[1],(const float*)d_in[2],
        (const float*)d_in[3],(const float*)d_in[4],(const float*)d_in[5],
        (const float*)d_in[6],(const float*)d_in[7],(const float*)d_in[8],
        (float*)d_out);
}